// round 4
// baseline (speedup 1.0000x reference)
#include <cuda_runtime.h>
#include <cstdint>

// Problem constants
#define BB   128   // batch
#define LL   196   // encoder length
#define EE   2048  // encoder dim
#define DD   1024  // decoder dim
#define AA   1024  // attention dim

// GEMM tile
#define Bb_M 128
#define Bb_N 128
#define Bb_K 32
// smem words per buffer: A frag 8192 (incl hi/lo) + B frag 8192
#define A_WORDS 8192
#define BUF_WORDS 16384

// ---------------- device scratch (no allocations allowed) ----------------
__device__ float g_decq[BB * AA];        // Wd @ h + bd           [128,1024]
__device__ float g_u[BB * EE];           // Wq^T @ dec_q          [128,2048]
__device__ float g_part[1 << 21];        // 8MB split-K partials
__device__ float g_fpart[2 * BB * EE];   // fused partial sums (unnormalized)
__device__ float g_fden[2 * BB];         // fused partial denominators

// ---------------- tf32 helpers ----------------
__device__ __forceinline__ uint32_t tf32_hi(float x) {
    uint32_t h;
    asm("cvt.rna.tf32.f32 %0, %1;" : "=r"(h) : "f"(x));
    return h;
}
__device__ __forceinline__ void split2(float x, uint32_t& hi, uint32_t& lo) {
    hi = tf32_hi(x);
    lo = tf32_hi(x - __uint_as_float(hi));
}

__device__ __forceinline__ void mma_tf32(float* c, const uint32_t* a,
                                         uint32_t b0, uint32_t b1) {
    asm volatile(
        "mma.sync.aligned.m16n8k8.row.col.f32.tf32.tf32.f32 "
        "{%0,%1,%2,%3}, {%4,%5,%6,%7}, {%8,%9}, {%0,%1,%2,%3};"
        : "+f"(c[0]), "+f"(c[1]), "+f"(c[2]), "+f"(c[3])
        : "r"(a[0]), "r"(a[1]), "r"(a[2]), "r"(a[3]), "r"(b0), "r"(b1));
}

// =====================================================================
// Tensor-core tf32x3 GEMM, fragment-major smem, split-K partials:
//   part[s][m][n] = sum_{k in chunk s} X[m,k] * W(k,n)
//   NN=true : W is [K,N] row-major;  NN=false: W is [N,K] row-major
// Block tile 128x128, K-step 32. 256 threads = 8 warps (4M x 2N),
// warp tile 32x64. Fragment-major layout:
//   A: tile=(row>>4)*4+ks (32 tiles), per tile 32 lanes x 8 words
//      [hi a0..a3 | lo a0..a3];  lane=(group*4+tg); v=rowhalf+2*khalf
//   B: tile=(n>>3)*4+ks (64 tiles), per tile 32 lanes x 4 words
//      [bh_k0, bh_k1, bl_k0, bl_k1]
// Inner loop: per ks, per warp-thread: 4+8 = 12 LDS.128 for 48 MMAs.
// XSEL: 0 -> X param, 1 -> g_decq, 2 -> g_fpart[0]+g_fpart[1]
// =====================================================================
template <bool NN, int XSEL>
__global__ void __launch_bounds__(256)
gemm_tc(const float* __restrict__ Xp, const float* __restrict__ W,
        int K, int N, int kchunk) {
    extern __shared__ uint32_t smw[];

    const float* X = (XSEL == 1) ? (const float*)g_decq : Xp;

    const int t     = threadIdx.x;
    const int warp  = t >> 5;
    const int lane  = t & 31;
    const int group = lane >> 2;    // 0..7
    const int tg    = lane & 3;     // 0..3
    const int wm    = warp & 3;     // 0..3  (M, 32 rows each)
    const int wn    = warp >> 2;    // 0..1  (N, 64 cols each)
    const int n0    = blockIdx.x * Bb_N;
    const int k0    = blockIdx.y * kchunk;

    float c[2][8][4];
#pragma unroll
    for (int mi = 0; mi < 2; mi++)
#pragma unroll
        for (int ni = 0; ni < 8; ni++)
#pragma unroll
            for (int r = 0; r < 4; r++) c[mi][ni][r] = 0.f;

    float4 ra[4];   // A tile: 128x32 = 1024 float4 / 256 thr
    float4 rb[4];   // B tile: 32x128 = 1024 float4 / 256 thr

    // ---- load tile (gmem -> regs)
    auto loadA = [&](int kt) {
#pragma unroll
        for (int j = 0; j < 4; j++) {
            const int idx = t + 256 * j;
            const int row = idx >> 3;
            const int kq  = idx & 7;
            if (XSEL == 2) {
                float4 p0 = *reinterpret_cast<const float4*>(
                    g_fpart + (size_t)row * EE + kt + kq * 4);
                float4 p1 = *reinterpret_cast<const float4*>(
                    g_fpart + (size_t)(BB + row) * EE + kt + kq * 4);
                ra[j] = make_float4(p0.x + p1.x, p0.y + p1.y, p0.z + p1.z, p0.w + p1.w);
            } else {
                ra[j] = *reinterpret_cast<const float4*>(X + (size_t)row * K + kt + kq * 4);
            }
        }
    };
    auto loadB = [&](int kt) {
        if (NN) {
#pragma unroll
            for (int j = 0; j < 4; j++) {
                const int idx = t + 256 * j;
                const int r   = idx >> 5;          // k row 0..31
                const int nq  = idx & 31;          // 32 float4 per row
                rb[j] = *reinterpret_cast<const float4*>(W + (size_t)(kt + r) * N + n0 + nq * 4);
            }
        } else {
#pragma unroll
            for (int j = 0; j < 4; j++) {
                const int idx = t + 256 * j;
                const int n   = idx >> 3;          // n row 0..127
                const int kq  = idx & 7;
                rb[j] = *reinterpret_cast<const float4*>(W + (size_t)(n0 + n) * K + kt + kq * 4);
            }
        }
    };
    // ---- split + store into fragment-major planes
    auto storeAB = [&](int bb) {
        uint32_t* bufA = smw + bb * BUF_WORDS;
        uint32_t* bufB = bufA + A_WORDS;
#pragma unroll
        for (int j = 0; j < 4; j++) {
            const int idx = t + 256 * j;
            const int row = idx >> 3;
            const int kq  = idx & 7;
            const int ks    = kq >> 1;
            const int khalf = kq & 1;
            const int v     = ((row >> 3) & 1) + 2 * khalf;  // rowhalf + 2*khalf
            uint32_t* base = bufA + (((row >> 4) * 4 + ks) << 8) + ((row & 7) << 5) + v;
            const float vals[4] = {ra[j].x, ra[j].y, ra[j].z, ra[j].w};
#pragma unroll
            for (int jj = 0; jj < 4; jj++) {       // tg = jj
                uint32_t h, l;
                split2(vals[jj], h, l);
                base[jj * 8]     = h;
                base[jj * 8 + 4] = l;
            }
        }
        if (NN) {
#pragma unroll
            for (int j = 0; j < 4; j++) {
                const int idx = t + 256 * j;
                const int r   = idx >> 5;
                const int nq  = idx & 31;
                const int ks    = r >> 3;
                const int tgr   = r & 3;
                const int khalf = (r >> 2) & 1;
                const float vals[4] = {rb[j].x, rb[j].y, rb[j].z, rb[j].w};
#pragma unroll
                for (int jj = 0; jj < 4; jj++) {
                    const int n = nq * 4 + jj;
                    uint32_t* base = bufB + (((n >> 3) * 4 + ks) << 7)
                                   + (((n & 7) * 4 + tgr) << 2);
                    uint32_t h, l;
                    split2(vals[jj], h, l);
                    base[khalf]     = h;
                    base[khalf + 2] = l;
                }
            }
        } else {
#pragma unroll
            for (int j = 0; j < 4; j++) {
                const int idx = t + 256 * j;
                const int n   = idx >> 3;
                const int kq  = idx & 7;
                const int ks    = kq >> 1;
                const int khalf = kq & 1;
                uint32_t* tb = bufB + (((n >> 3) * 4 + ks) << 7) + (((n & 7) * 4) << 2);
                const float vals[4] = {rb[j].x, rb[j].y, rb[j].z, rb[j].w};
#pragma unroll
                for (int jj = 0; jj < 4; jj++) {   // tg = jj
                    uint32_t h, l;
                    split2(vals[jj], h, l);
                    uint32_t* base = tb + (jj << 2);
                    base[khalf]     = h;
                    base[khalf + 2] = l;
                }
            }
        }
    };
    // ---- compute one K-32 tile (pure LDS.128 + MMA)
    auto compute = [&](int bb) {
        const uint32_t* bufA = smw + bb * BUF_WORDS;
        const uint32_t* bufB = bufA + A_WORDS;
#pragma unroll
        for (int ks = 0; ks < 4; ks++) {
            uint4 ah[2], al[2];
#pragma unroll
            for (int mi = 0; mi < 2; mi++) {
                const uint32_t* Af = bufA + (((wm * 2 + mi) * 4 + ks) << 8) + lane * 8;
                ah[mi] = *reinterpret_cast<const uint4*>(Af);
                al[mi] = *reinterpret_cast<const uint4*>(Af + 4);
            }
#pragma unroll
            for (int ni = 0; ni < 8; ni++) {
                const uint32_t* Bf = bufB + (((wn * 8 + ni) * 4 + ks) << 7) + lane * 4;
                uint4 bv = *reinterpret_cast<const uint4*>(Bf);
#pragma unroll
                for (int mi = 0; mi < 2; mi++) {
                    mma_tf32(c[mi][ni], reinterpret_cast<const uint32_t*>(&ah[mi]), bv.x, bv.y);
                    mma_tf32(c[mi][ni], reinterpret_cast<const uint32_t*>(&ah[mi]), bv.z, bv.w);
                    mma_tf32(c[mi][ni], reinterpret_cast<const uint32_t*>(&al[mi]), bv.x, bv.y);
                }
            }
        }
    };

    // ---- pipelined main loop (reg prefetch + double-buffered smem)
    loadA(k0);
    loadB(k0);
    storeAB(0);
    __syncthreads();

    const int nkb = kchunk >> 5;
    for (int kb = 0; kb < nkb; kb++) {
        const int cur = kb & 1;
        if (kb + 1 < nkb) {
            loadA(k0 + (kb + 1) * 32);
            loadB(k0 + (kb + 1) * 32);
        }
        compute(cur);
        if (kb + 1 < nkb) {
            storeAB(cur ^ 1);
        }
        __syncthreads();
    }

    // ---- write partials
    float* pb = g_part + (size_t)blockIdx.y * (BB * N);
#pragma unroll
    for (int mi = 0; mi < 2; mi++) {
        const int row0 = wm * 32 + mi * 16 + group;
#pragma unroll
        for (int ni = 0; ni < 8; ni++) {
            const int col = n0 + wn * 64 + ni * 8 + 2 * tg;
            float2 v01 = {c[mi][ni][0], c[mi][ni][1]};
            float2 v23 = {c[mi][ni][2], c[mi][ni][3]};
            *reinterpret_cast<float2*>(pb + (size_t)row0 * N + col) = v01;
            *reinterpret_cast<float2*>(pb + (size_t)(row0 + 8) * N + col) = v23;
        }
    }
}

// =====================================================================
// Split-K reduce (+bias, +optional per-row 1/sum(w) scale for context)
// OUTSEL: 0 -> out param, 1 -> g_decq, 2 -> g_u
// =====================================================================
template <int OUTSEL, bool SCALE>
__global__ void reduce_add_kernel(float* __restrict__ outp,
                                  const float* __restrict__ bias,
                                  int S, int MN, int N) {
    float* out = (OUTSEL == 0) ? outp : (OUTSEL == 1 ? (float*)g_decq : (float*)g_u);
    int i = (blockIdx.x * blockDim.x + threadIdx.x) * 4;
    if (i >= MN) return;
    float4 s = *reinterpret_cast<const float4*>(g_part + i);
    for (int k = 1; k < S; k++) {
        float4 v = *reinterpret_cast<const float4*>(g_part + (size_t)k * MN + i);
        s.x += v.x; s.y += v.y; s.z += v.z; s.w += v.w;
    }
    if (SCALE) {
        const int m = i / N;
        const float inv = 1.f / (g_fden[m] + g_fden[BB + m]);
        s.x *= inv; s.y *= inv; s.z *= inv; s.w *= inv;
    }
    if (bias) {
        float4 bv = *reinterpret_cast<const float4*>(bias + (i % N));
        s.x += bv.x; s.y += bv.y; s.z += bv.z; s.w += bv.w;
    }
    *reinterpret_cast<float4*>(out + i) = s;
}

// =====================================================================
// Fused attention pass, split 2-ways over L. grid (BB, 2), 512 threads.
// Computes c[b]=bq.dec_q[b] inline (identical in both split CTAs).
// 8-row chunks: phase (a) pair-warp dot products (DRAM stream),
// phase (b) weighted sum re-reads the 64KB chunk from L1.
// Writes UNNORMALIZED partial sums + partial denominators.
// =====================================================================
__global__ void fused_attn_kernel(const float* __restrict__ enc,
                                  const float* __restrict__ bq) {
    const int b    = blockIdx.x;
    const int sp   = blockIdx.y;       // 0..1
    const int t    = threadIdx.x;      // 512
    const int warp = t >> 5;
    const int lane = t & 31;
    const int lstart = sp * 98;
    const int lend   = (lstart + 98 < LL) ? lstart + 98 : LL;

    __shared__ float u_s[EE];
    __shared__ float cred[16];
    __shared__ float c_sh;
    __shared__ float pdot[8][2];
    __shared__ float wexp_s[8];
    __shared__ float wden_sh;

    // stage u[b]
    reinterpret_cast<float4*>(u_s)[t] =
        reinterpret_cast<const float4*>(g_u + (size_t)b * EE)[t];

    // c[b] = bq . dec_q[b]   (fixed order; both split-CTAs identical)
    {
        const float* dq = g_decq + (size_t)b * AA;
        float s = bq[t] * dq[t] + bq[t + 512] * dq[t + 512];
#pragma unroll
        for (int o = 16; o > 0; o >>= 1) s += __shfl_xor_sync(0xffffffffu, s, o);
        if (lane == 0) cred[warp] = s;
    }
    if (t == 0) wden_sh = 0.f;
    __syncthreads();
    if (t == 0) {
        float tot = 0.f;
        for (int i = 0; i < 16; i++) tot += cred[i];
        c_sh = tot;
    }
    __syncthreads();
    const float c_b = c_sh;

    const float* encb = enc + (size_t)b * LL * EE;
    float4 macc = {0.f, 0.f, 0.f, 0.f};

    for (int c0 = lstart; c0 < lend; c0 += 8) {
        const int nr = (lend - c0) < 8 ? (lend - c0) : 8;
        const int lw   = warp >> 1;    // row within chunk
        const int half = warp & 1;     // which half of the 2048-dim dot

        if (lw < nr) {
            const float4* row4 =
                reinterpret_cast<const float4*>(encb + (size_t)(c0 + lw) * EE) + half * 256;
            const float4* us4 = reinterpret_cast<const float4*>(u_s) + half * 256;
            float d = 0.f;
#pragma unroll
            for (int i = 0; i < 8; i++) {
                const int f = lane + 32 * i;
                float4 v  = row4[f];
                float4 uu = us4[f];
                d += v.x * uu.x + v.y * uu.y + v.z * uu.z + v.w * uu.w;
            }
#pragma unroll
            for (int o = 16; o > 0; o >>= 1)
                d += __shfl_xor_sync(0xffffffffu, d, o);
            if (lane == 0) pdot[lw][half] = d;
        }
        __syncthreads();

        if (t < nr)
            wexp_s[t] = __expf(tanhf(pdot[t][0] + pdot[t][1] + c_b));
        __syncthreads();

        if (t == 0) {
            float acc = 0.f;
            for (int r = 0; r < nr; r++) acc += wexp_s[r];
            wden_sh += acc;
        }
        const float4* base = reinterpret_cast<const float4*>(encb + (size_t)c0 * EE) + t;
        for (int r = 0; r < nr; r++) {
            const float wv = wexp_s[r];
            float4 v = base[(size_t)r * (EE / 4)];
            macc.x += wv * v.x; macc.y += wv * v.y;
            macc.z += wv * v.z; macc.w += wv * v.w;
        }
        __syncthreads();
    }

    float* pp = g_fpart + ((size_t)sp * BB + b) * EE;
    reinterpret_cast<float4*>(pp)[t] = macc;
    if (t == 0) g_fden[sp * BB + b] = wden_sh;
}

// =====================================================================
// Launcher
// =====================================================================
extern "C" void kernel_launch(void* const* d_in, const int* in_sizes, int n_in,
                              void* d_out, int out_size) {
    const float* enc = (const float*)d_in[0];  // [128,196,2048]
    const float* dh  = (const float*)d_in[1];  // [128,1024]
    const float* Wq  = (const float*)d_in[2];  // [1024,2048]  (A,E)
    const float* bq  = (const float*)d_in[3];  // [1024]
    const float* Wv  = (const float*)d_in[4];  // [1024,2048]  (A,E)
    const float* bv  = (const float*)d_in[5];  // [1024]
    const float* Wd  = (const float*)d_in[6];  // [1024,1024]  (A,D)
    const float* bd  = (const float*)d_in[7];  // [1024]
    float* out = (float*)d_out;                // [128,1024]

    const int smemsz = 2 * BUF_WORDS * 4;      // 128KB dynamic
    static bool attr_done = false;
    if (!attr_done) {
        cudaFuncSetAttribute(gemm_tc<false, 0>, cudaFuncAttributeMaxDynamicSharedMemorySize, smemsz);
        cudaFuncSetAttribute(gemm_tc<true, 1>,  cudaFuncAttributeMaxDynamicSharedMemorySize, smemsz);
        cudaFuncSetAttribute(gemm_tc<false, 2>, cudaFuncAttributeMaxDynamicSharedMemorySize, smemsz);
        attr_done = true;
    }

    // 1) dec_q = h @ Wd^T + bd   (NT, K=D=1024, split 16 -> 8x16 = 128 CTAs)
    gemm_tc<false, 0><<<dim3(AA / Bb_N, 16), 256, smemsz>>>(dh, Wd, DD, AA, DD / 16);
    reduce_add_kernel<1, false><<<(BB * AA) / 1024, 256>>>(nullptr, bd, 16, BB * AA, AA);

    // 2) u = dec_q @ Wq          (NN, K=A=1024, split 8 -> 16x8 = 128 CTAs)
    gemm_tc<true, 1><<<dim3(EE / Bb_N, 8), 256, smemsz>>>(nullptr, Wq, AA, EE, AA / 8);
    reduce_add_kernel<2, false><<<(BB * EE) / 1024, 256>>>(nullptr, nullptr, 8, BB * EE, EE);

    // 3) fused: c + energies + softmax weights + weighted encoder sum (split 2 over L)
    fused_attn_kernel<<<dim3(BB, 2), 512>>>(enc, bq);

    // 4) context = (P0+P1) @ Wv^T, then *1/sum(w) + bv in reduce epilogue
    //    (NT, K=E=2048, split 16 -> 8x16 = 128 CTAs)
    gemm_tc<false, 2><<<dim3(AA / Bb_N, 16), 256, smemsz>>>(nullptr, Wv, EE, AA, EE / 16);
    reduce_add_kernel<0, true><<<(BB * AA) / 1024, 256>>>(out, bv, 16, BB * AA, AA);
}

// round 5
// speedup vs baseline: 1.2855x; 1.2855x over previous
#include <cuda_runtime.h>
#include <cstdint>

// Problem constants
#define BB   128   // batch
#define LL   196   // encoder length
#define EE   2048  // encoder dim
#define DD   1024  // decoder dim
#define AA   1024  // attention dim

// ---------------- device scratch (no allocations allowed) ----------------
__device__ float g_decq[BB * AA];        // Wd @ h + bd           [128,1024]
__device__ float g_u[BB * EE];           // Wq^T @ dec_q          [128,2048]
__device__ float g_part[1 << 21];        // 8MB split-K partials
__device__ float g_fpart[2 * BB * EE];   // fused partial sums (unnormalized)
__device__ float g_fden[2 * BB];         // fused partial denominators

// ---------------- tf32 helpers ----------------
__device__ __forceinline__ uint32_t tf32_hi(float x) {
    uint32_t h;
    asm("cvt.rna.tf32.f32 %0, %1;" : "=r"(h) : "f"(x));
    return h;
}
__device__ __forceinline__ void split2(float x, uint32_t& hi, uint32_t& lo) {
    hi = tf32_hi(x);
    lo = tf32_hi(x - __uint_as_float(hi));
}

__device__ __forceinline__ void mma_tf32(float* c, const uint32_t* a,
                                         uint32_t b0, uint32_t b1) {
    asm volatile(
        "mma.sync.aligned.m16n8k8.row.col.f32.tf32.tf32.f32 "
        "{%0,%1,%2,%3}, {%4,%5,%6,%7}, {%8,%9}, {%0,%1,%2,%3};"
        : "+f"(c[0]), "+f"(c[1]), "+f"(c[2]), "+f"(c[3])
        : "r"(a[0]), "r"(a[1]), "r"(a[2]), "r"(a[3]), "r"(b0), "r"(b1));
}

// Smem: A planes as in R3 (conflict-free store+read); B packed fragment-major:
//   Bp[buf][bi][slot][w], bi = ntile*4+ks (32 blocks, stride 132 words for
//   bank spread), slot = (n&7)*4 + (k&3) = lane, w: 0=hi(k),1=hi(k+4),2=lo(k),3=lo(k+4)
struct SmemGemm {
    uint32_t Ahi[2][128][36];
    uint32_t Alo[2][128][36];
    uint32_t Bp[2][32 * 132];
};

// =====================================================================
// Tensor-core tf32x3 GEMM, split-K partials:
//   part[s][m][n] = sum_{k in chunk s} X[m,k] * W(k,n)
//   NN=true : W is [K,N] row-major;  NN=false: W is [N,K] row-major
// 256 threads = 8 warps (4M x 2N), block tile 128x64, K-step 32.
// Inner loop per ks: 16 scalar LDS (A) + 4x LDS.128 (B) + 24 MMA.
// XSEL: 0 -> X param, 1 -> g_decq, 2 -> g_fpart[0]+g_fpart[1]
// =====================================================================
template <bool NN, int XSEL>
__global__ void __launch_bounds__(256)
gemm_tc(const float* __restrict__ Xp, const float* __restrict__ W,
        int K, int N, int kchunk) {
    extern __shared__ SmemGemm sm_g[];
    SmemGemm* s = sm_g;

    const float* X = (XSEL == 1) ? (const float*)g_decq : Xp;

    const int t     = threadIdx.x;
    const int warp  = t >> 5;
    const int lane  = t & 31;
    const int group = lane >> 2;    // 0..7
    const int tg    = lane & 3;     // 0..3
    const int wm    = warp & 3;     // 0..3  (M)
    const int wn    = warp >> 2;    // 0..1  (N)
    const int n0    = blockIdx.x * 64;
    const int k0    = blockIdx.y * kchunk;

    float c[2][4][4];
#pragma unroll
    for (int mi = 0; mi < 2; mi++)
#pragma unroll
        for (int ni = 0; ni < 4; ni++)
#pragma unroll
            for (int r = 0; r < 4; r++) c[mi][ni][r] = 0.f;

    float4 ra[4];
    float4 rb[2];

    // ---- load tile (gmem -> regs)
    auto loadA = [&](int kt) {
#pragma unroll
        for (int j = 0; j < 4; j++) {
            const int idx = t + 256 * j;
            const int row = idx >> 3;
            const int kq  = idx & 7;
            if (XSEL == 2) {
                float4 p0 = *reinterpret_cast<const float4*>(
                    g_fpart + (size_t)row * EE + kt + kq * 4);
                float4 p1 = *reinterpret_cast<const float4*>(
                    g_fpart + (size_t)(BB + row) * EE + kt + kq * 4);
                ra[j] = make_float4(p0.x + p1.x, p0.y + p1.y, p0.z + p1.z, p0.w + p1.w);
            } else {
                ra[j] = *reinterpret_cast<const float4*>(X + (size_t)row * K + kt + kq * 4);
            }
        }
    };
    auto loadB = [&](int kt) {
        if (NN) {
#pragma unroll
            for (int j = 0; j < 2; j++) {
                const int idx = t + 256 * j;
                const int r   = idx >> 4;
                const int nq  = idx & 15;
                rb[j] = *reinterpret_cast<const float4*>(W + (size_t)(kt + r) * N + n0 + nq * 4);
            }
        } else {
#pragma unroll
            for (int j = 0; j < 2; j++) {
                const int idx = t + 256 * j;
                const int n   = idx >> 3;
                const int kq  = idx & 7;
                rb[j] = *reinterpret_cast<const float4*>(W + (size_t)(n0 + n) * K + kt + kq * 4);
            }
        }
    };
    // ---- split + store (regs -> smem)
    auto storeAB = [&](int bb) {
        // A: same as R3 (conflict-free)
#pragma unroll
        for (int j = 0; j < 4; j++) {
            const int idx = t + 256 * j;
            const int row = idx >> 3;
            const int kq  = idx & 7;
            uint4 h, l;
            split2(ra[j].x, h.x, l.x);
            split2(ra[j].y, h.y, l.y);
            split2(ra[j].z, h.z, l.z);
            split2(ra[j].w, h.w, l.w);
            *reinterpret_cast<uint4*>(&s->Ahi[bb][row][kq * 4]) = h;
            *reinterpret_cast<uint4*>(&s->Alo[bb][row][kq * 4]) = l;
        }
        // B: packed fragment-major
        uint32_t* bp = s->Bp[bb];
        if (NN) {
#pragma unroll
            for (int j = 0; j < 2; j++) {
                const int idx  = t + 256 * j;
                const int r    = idx >> 4;    // k in 0..31
                const int nq   = idx & 15;
                const int ks    = r >> 3;
                const int khalf = (r >> 2) & 1;
                const int tgk   = r & 3;
                const float vals[4] = {rb[j].x, rb[j].y, rb[j].z, rb[j].w};
#pragma unroll
                for (int jj = 0; jj < 4; jj++) {
                    const int n  = nq * 4 + jj;
                    const int bi = (n >> 3) * 4 + ks;
                    uint32_t* base = bp + bi * 132 + ((n & 7) * 4 + tgk) * 4;
                    uint32_t h, l;
                    split2(vals[jj], h, l);
                    base[khalf]     = h;
                    base[khalf + 2] = l;
                }
            }
        } else {
#pragma unroll
            for (int j = 0; j < 2; j++) {
                const int idx = t + 256 * j;
                const int n   = idx >> 3;     // 0..63
                const int kq  = idx & 7;
                const int ks    = kq >> 1;
                const int khalf = kq & 1;
                const int bi    = (n >> 3) * 4 + ks;
                uint32_t* tb = bp + bi * 132 + ((n & 7) * 4) * 4;
                const float vals[4] = {rb[j].x, rb[j].y, rb[j].z, rb[j].w};
#pragma unroll
                for (int jj = 0; jj < 4; jj++) {  // k = kq*4+jj -> tg = jj
                    uint32_t h, l;
                    split2(vals[jj], h, l);
                    uint32_t* base = tb + jj * 4;
                    base[khalf]     = h;
                    base[khalf + 2] = l;
                }
            }
        }
    };
    // ---- compute one K-32 tile
    auto compute = [&](int bb) {
        const uint32_t* bp = s->Bp[bb];
#pragma unroll
        for (int ks = 0; ks < 4; ks++) {
            const int koff = ks * 8;
            uint32_t ah[2][4], al[2][4];
#pragma unroll
            for (int mi = 0; mi < 2; mi++) {
                const int rm = wm * 32 + mi * 16 + group;
                ah[mi][0] = s->Ahi[bb][rm][koff + tg];
                ah[mi][1] = s->Ahi[bb][rm + 8][koff + tg];
                ah[mi][2] = s->Ahi[bb][rm][koff + tg + 4];
                ah[mi][3] = s->Ahi[bb][rm + 8][koff + tg + 4];
                al[mi][0] = s->Alo[bb][rm][koff + tg];
                al[mi][1] = s->Alo[bb][rm + 8][koff + tg];
                al[mi][2] = s->Alo[bb][rm][koff + tg + 4];
                al[mi][3] = s->Alo[bb][rm + 8][koff + tg + 4];
            }
#pragma unroll
            for (int ni = 0; ni < 4; ni++) {
                const uint32_t* Bf = bp + ((wn * 4 + ni) * 4 + ks) * 132 + lane * 4;
                uint4 bv = *reinterpret_cast<const uint4*>(Bf);
#pragma unroll
                for (int mi = 0; mi < 2; mi++) {
                    mma_tf32(c[mi][ni], ah[mi], bv.x, bv.y);
                    mma_tf32(c[mi][ni], ah[mi], bv.z, bv.w);
                    mma_tf32(c[mi][ni], al[mi], bv.x, bv.y);
                }
            }
        }
    };

    // ---- pipelined main loop
    loadA(k0);
    loadB(k0);
    storeAB(0);
    __syncthreads();

    const int nkb = kchunk >> 5;
    for (int kb = 0; kb < nkb; kb++) {
        const int cur = kb & 1;
        if (kb + 1 < nkb) {
            loadA(k0 + (kb + 1) * 32);
            loadB(k0 + (kb + 1) * 32);
        }
        compute(cur);
        if (kb + 1 < nkb) storeAB(cur ^ 1);
        __syncthreads();
    }

    // ---- write partials
    float* pb = g_part + (size_t)blockIdx.y * (BB * N);
#pragma unroll
    for (int mi = 0; mi < 2; mi++) {
        const int row0 = wm * 32 + mi * 16 + group;
#pragma unroll
        for (int ni = 0; ni < 4; ni++) {
            const int col = n0 + wn * 32 + ni * 8 + 2 * tg;
            float2 v01 = {c[mi][ni][0], c[mi][ni][1]};
            float2 v23 = {c[mi][ni][2], c[mi][ni][3]};
            *reinterpret_cast<float2*>(pb + (size_t)row0 * N + col) = v01;
            *reinterpret_cast<float2*>(pb + (size_t)(row0 + 8) * N + col) = v23;
        }
    }
}

// =====================================================================
// Split-K reduce, compile-time S (unrolled -> S loads in flight).
// OUTSEL: 0 -> out param, 1 -> g_decq, 2 -> g_u
// =====================================================================
template <int OUTSEL, bool SCALE, int S>
__global__ void reduce_add_kernel(float* __restrict__ outp,
                                  const float* __restrict__ bias,
                                  int MN, int N) {
    float* out = (OUTSEL == 0) ? outp : (OUTSEL == 1 ? (float*)g_decq : (float*)g_u);
    int i = (blockIdx.x * blockDim.x + threadIdx.x) * 4;
    if (i >= MN) return;
    float4 v[S];
#pragma unroll
    for (int k = 0; k < S; k++)
        v[k] = *reinterpret_cast<const float4*>(g_part + (size_t)k * MN + i);
    float4 sv = v[0];
#pragma unroll
    for (int k = 1; k < S; k++) {
        sv.x += v[k].x; sv.y += v[k].y; sv.z += v[k].z; sv.w += v[k].w;
    }
    if (SCALE) {
        const int m = i / N;
        const float inv = 1.f / (g_fden[m] + g_fden[BB + m]);
        sv.x *= inv; sv.y *= inv; sv.z *= inv; sv.w *= inv;
    }
    if (bias) {
        float4 bv = *reinterpret_cast<const float4*>(bias + (i % N));
        sv.x += bv.x; sv.y += bv.y; sv.z += bv.z; sv.w += bv.w;
    }
    *reinterpret_cast<float4*>(out + i) = sv;
}

// =====================================================================
// Fused attention pass, split 2-ways over L. grid (BB, 2), 512 threads.
// Computes c[b]=bq.dec_q[b] inline (identical in both split CTAs).
// 8-row chunks: phase (a) pair-warp dot products (DRAM stream),
// phase (b) weighted sum re-reads the 64KB chunk from L1.
// Writes UNNORMALIZED partial sums + partial denominators.
// =====================================================================
__global__ void fused_attn_kernel(const float* __restrict__ enc,
                                  const float* __restrict__ bq) {
    const int b    = blockIdx.x;
    const int sp   = blockIdx.y;       // 0..1
    const int t    = threadIdx.x;      // 512
    const int warp = t >> 5;
    const int lane = t & 31;
    const int lstart = sp * 98;
    const int lend   = (lstart + 98 < LL) ? lstart + 98 : LL;

    __shared__ float u_s[EE];
    __shared__ float cred[16];
    __shared__ float c_sh;
    __shared__ float pdot[8][2];
    __shared__ float wexp_s[8];
    __shared__ float wden_sh;

    // stage u[b]
    reinterpret_cast<float4*>(u_s)[t] =
        reinterpret_cast<const float4*>(g_u + (size_t)b * EE)[t];

    // c[b] = bq . dec_q[b]   (fixed order; both split-CTAs identical)
    {
        const float* dq = g_decq + (size_t)b * AA;
        float sv = bq[t] * dq[t] + bq[t + 512] * dq[t + 512];
#pragma unroll
        for (int o = 16; o > 0; o >>= 1) sv += __shfl_xor_sync(0xffffffffu, sv, o);
        if (lane == 0) cred[warp] = sv;
    }
    if (t == 0) wden_sh = 0.f;
    __syncthreads();
    if (t == 0) {
        float tot = 0.f;
        for (int i = 0; i < 16; i++) tot += cred[i];
        c_sh = tot;
    }
    __syncthreads();
    const float c_b = c_sh;

    const float* encb = enc + (size_t)b * LL * EE;
    float4 macc = {0.f, 0.f, 0.f, 0.f};

    for (int c0 = lstart; c0 < lend; c0 += 8) {
        const int nr = (lend - c0) < 8 ? (lend - c0) : 8;
        const int lw   = warp >> 1;    // row within chunk
        const int half = warp & 1;     // which half of the 2048-dim dot

        if (lw < nr) {
            const float4* row4 =
                reinterpret_cast<const float4*>(encb + (size_t)(c0 + lw) * EE) + half * 256;
            const float4* us4 = reinterpret_cast<const float4*>(u_s) + half * 256;
            float d = 0.f;
#pragma unroll
            for (int i = 0; i < 8; i++) {
                const int f = lane + 32 * i;
                float4 v  = row4[f];
                float4 uu = us4[f];
                d += v.x * uu.x + v.y * uu.y + v.z * uu.z + v.w * uu.w;
            }
#pragma unroll
            for (int o = 16; o > 0; o >>= 1)
                d += __shfl_xor_sync(0xffffffffu, d, o);
            if (lane == 0) pdot[lw][half] = d;
        }
        __syncthreads();

        if (t < nr)
            wexp_s[t] = __expf(tanhf(pdot[t][0] + pdot[t][1] + c_b));
        __syncthreads();

        if (t == 0) {
            float acc = 0.f;
            for (int r = 0; r < nr; r++) acc += wexp_s[r];
            wden_sh += acc;
        }
        const float4* base = reinterpret_cast<const float4*>(encb + (size_t)c0 * EE) + t;
        for (int r = 0; r < nr; r++) {
            const float wv = wexp_s[r];
            float4 v = base[(size_t)r * (EE / 4)];
            macc.x += wv * v.x; macc.y += wv * v.y;
            macc.z += wv * v.z; macc.w += wv * v.w;
        }
        __syncthreads();
    }

    float* pp = g_fpart + ((size_t)sp * BB + b) * EE;
    reinterpret_cast<float4*>(pp)[t] = macc;
    if (t == 0) g_fden[sp * BB + b] = wden_sh;
}

// =====================================================================
// Launcher
// =====================================================================
extern "C" void kernel_launch(void* const* d_in, const int* in_sizes, int n_in,
                              void* d_out, int out_size) {
    const float* enc = (const float*)d_in[0];  // [128,196,2048]
    const float* dh  = (const float*)d_in[1];  // [128,1024]
    const float* Wq  = (const float*)d_in[2];  // [1024,2048]  (A,E)
    const float* bq  = (const float*)d_in[3];  // [1024]
    const float* Wv  = (const float*)d_in[4];  // [1024,2048]  (A,E)
    const float* bv  = (const float*)d_in[5];  // [1024]
    const float* Wd  = (const float*)d_in[6];  // [1024,1024]  (A,D)
    const float* bd  = (const float*)d_in[7];  // [1024]
    float* out = (float*)d_out;                // [128,1024]

    const int smemsz = (int)sizeof(SmemGemm);  // ~105KB dynamic
    cudaFuncSetAttribute(gemm_tc<false, 0>, cudaFuncAttributeMaxDynamicSharedMemorySize, smemsz);
    cudaFuncSetAttribute(gemm_tc<true, 1>,  cudaFuncAttributeMaxDynamicSharedMemorySize, smemsz);
    cudaFuncSetAttribute(gemm_tc<false, 2>, cudaFuncAttributeMaxDynamicSharedMemorySize, smemsz);

    // 1) dec_q = h @ Wd^T + bd   (NT, K=D=1024, split 8 -> 16x8 = 128 CTAs)
    gemm_tc<false, 0><<<dim3(AA / 64, 8), 256, smemsz>>>(dh, Wd, DD, AA, DD / 8);
    reduce_add_kernel<1, false, 8><<<(BB * AA) / 1024, 256>>>(nullptr, bd, BB * AA, AA);

    // 2) u = dec_q @ Wq          (NN, K=A=1024, split 4 -> 32x4 = 128 CTAs)
    gemm_tc<true, 1><<<dim3(EE / 64, 4), 256, smemsz>>>(nullptr, Wq, AA, EE, AA / 4);
    reduce_add_kernel<2, false, 4><<<(BB * EE) / 1024, 256>>>(nullptr, nullptr, BB * EE, EE);

    // 3) fused: c + energies + softmax weights + weighted encoder sum (split 2 over L)
    fused_attn_kernel<<<dim3(BB, 2), 512>>>(enc, bq);

    // 4) context = (P0+P1) @ Wv^T, then *1/sum(w) + bv in reduce epilogue
    //    (NT, K=E=2048, split 8 -> 16x8 = 128 CTAs)
    gemm_tc<false, 2><<<dim3(AA / 64, 8), 256, smemsz>>>(nullptr, Wv, EE, AA, EE / 8);
    reduce_add_kernel<0, true, 8><<<(BB * AA) / 1024, 256>>>(out, bv, BB * AA, AA);
}

// round 6
// speedup vs baseline: 1.8459x; 1.4359x over previous
#include <cuda_runtime.h>
#include <cstdint>

// Problem constants
#define BB   128   // batch
#define LL   196   // encoder length
#define EE   2048  // encoder dim
#define DD   1024  // decoder dim
#define AA   1024  // attention dim
#define USPLIT 4   // split-K of the u GEMM (fused kernel reduces these partials)

// ---------------- device scratch (no allocations allowed) ----------------
__device__ float g_decq[BB * AA];        // Wd @ h + bd           [128,1024]
__device__ float g_part[1 << 21];        // 8MB split-K partials (reused)
__device__ float g_fpart[2 * BB * EE];   // fused partial sums (unnormalized)
__device__ float g_fden[2 * BB];         // fused partial denominators

// ---------------- bf16 split helpers ----------------
// Split two consecutive-k floats into packed bf16x2 hi and lo words.
// wh = {lo16: bf16(x0), hi16: bf16(x1)}; wl captures the residuals.
__device__ __forceinline__ void pack2_bf(float x0, float x1,
                                         uint32_t& wh, uint32_t& wl) {
    asm("cvt.rn.bf16x2.f32 %0, %1, %2;" : "=r"(wh) : "f"(x1), "f"(x0));
    float h0 = __uint_as_float(wh << 16);
    float h1 = __uint_as_float(wh & 0xffff0000u);
    float l0 = x0 - h0;
    float l1 = x1 - h1;
    asm("cvt.rn.bf16x2.f32 %0, %1, %2;" : "=r"(wl) : "f"(l1), "f"(l0));
}

__device__ __forceinline__ void mma_bf16(float* c, const uint32_t* a,
                                         uint32_t b0, uint32_t b1) {
    asm volatile(
        "mma.sync.aligned.m16n8k16.row.col.f32.bf16.bf16.f32 "
        "{%0,%1,%2,%3}, {%4,%5,%6,%7}, {%8,%9}, {%0,%1,%2,%3};"
        : "+f"(c[0]), "+f"(c[1]), "+f"(c[2]), "+f"(c[3])
        : "r"(a[0]), "r"(a[1]), "r"(a[2]), "r"(a[3]), "r"(b0), "r"(b1));
}

// Smem: A planes [row][kpair] stride 20 (conflict-free frag reads),
// B packed fragment-major: Bp[bi][lane][w], bi = ntile*2 + ks16 (16 blocks,
// stride 132 words), lane = (n&7)*4 + tgk, w: [b0hi, b1hi, b0lo, b1lo].
struct SmemGemm {
    uint32_t Ah[2][128][20];
    uint32_t Al[2][128][20];
    uint32_t Bp[2][16 * 132];
};

// =====================================================================
// Tensor-core bf16x3 GEMM, split-K partials:
//   part[s][m][n] = sum_{k in chunk s} X[m,k] * W(k,n)
//   NN=true : W is [K,N] row-major;  NN=false: W is [N,K] row-major
// 256 threads = 8 warps (4M x 2N), block tile 128x64, K-step 32.
// Inner loop per ks16: 16 scalar LDS (A) + 4 LDS.128 (B) + 24 MMA(k16).
// XSEL: 0 -> X param, 1 -> g_decq, 2 -> g_fpart[0]+g_fpart[1]
// =====================================================================
template <bool NN, int XSEL>
__global__ void __launch_bounds__(256, 2)
gemm_tc(const float* __restrict__ Xp, const float* __restrict__ W,
        int K, int N, int kchunk) {
    extern __shared__ SmemGemm sm_g[];
    SmemGemm* s = sm_g;

    const float* X = (XSEL == 1) ? (const float*)g_decq : Xp;

    const int t     = threadIdx.x;
    const int warp  = t >> 5;
    const int lane  = t & 31;
    const int group = lane >> 2;    // 0..7
    const int tg    = lane & 3;     // 0..3
    const int wm    = warp & 3;     // 0..3  (M)
    const int wn    = warp >> 2;    // 0..1  (N)
    const int n0    = blockIdx.x * 64;
    const int k0    = blockIdx.y * kchunk;

    float c[2][4][4];
#pragma unroll
    for (int mi = 0; mi < 2; mi++)
#pragma unroll
        for (int ni = 0; ni < 4; ni++)
#pragma unroll
            for (int r = 0; r < 4; r++) c[mi][ni][r] = 0.f;

    float4 ra[4];
    float4 rb[2];

    // ---- load tile (gmem -> regs)
    auto loadA = [&](int kt) {
#pragma unroll
        for (int j = 0; j < 4; j++) {
            const int idx = t + 256 * j;
            const int row = idx >> 3;
            const int kq  = idx & 7;
            if (XSEL == 2) {
                float4 p0 = *reinterpret_cast<const float4*>(
                    g_fpart + (size_t)row * EE + kt + kq * 4);
                float4 p1 = *reinterpret_cast<const float4*>(
                    g_fpart + (size_t)(BB + row) * EE + kt + kq * 4);
                ra[j] = make_float4(p0.x + p1.x, p0.y + p1.y, p0.z + p1.z, p0.w + p1.w);
            } else {
                ra[j] = *reinterpret_cast<const float4*>(X + (size_t)row * K + kt + kq * 4);
            }
        }
    };
    auto loadB = [&](int kt) {
        if (NN) {
            // thread -> (kp = t>>4 in 0..15, nq = t&15); rows 2kp, 2kp+1
            const int kp = t >> 4;
            const int nq = t & 15;
            rb[0] = *reinterpret_cast<const float4*>(W + (size_t)(kt + 2 * kp) * N + n0 + nq * 4);
            rb[1] = *reinterpret_cast<const float4*>(W + (size_t)(kt + 2 * kp + 1) * N + n0 + nq * 4);
        } else {
#pragma unroll
            for (int j = 0; j < 2; j++) {
                const int idx = t + 256 * j;
                const int n   = idx >> 3;
                const int kq  = idx & 7;
                rb[j] = *reinterpret_cast<const float4*>(W + (size_t)(n0 + n) * K + kt + kq * 4);
            }
        }
    };
    // ---- split to bf16 hi/lo + store (regs -> smem)
    auto storeAB = [&](int bb) {
        // A: [row][kpair] words, pair = (k, k+1)
#pragma unroll
        for (int j = 0; j < 4; j++) {
            const int idx = t + 256 * j;
            const int row = idx >> 3;
            const int kq  = idx & 7;
            uint32_t wh0, wl0, wh1, wl1;
            pack2_bf(ra[j].x, ra[j].y, wh0, wl0);
            pack2_bf(ra[j].z, ra[j].w, wh1, wl1);
            *reinterpret_cast<uint2*>(&s->Ah[bb][row][2 * kq]) = make_uint2(wh0, wh1);
            *reinterpret_cast<uint2*>(&s->Al[bb][row][2 * kq]) = make_uint2(wl0, wl1);
        }
        // B packed fragment-major
        uint32_t* bp = s->Bp[bb];
        if (NN) {
            const int kp   = t >> 4;      // pair index 0..15
            const int nq   = t & 15;
            const int ks16 = kp >> 3;
            const int pp   = kp & 7;
            const int breg = (pp >= 4) ? 1 : 0;
            const int tgk  = pp & 3;
            const float e0[4] = {rb[0].x, rb[0].y, rb[0].z, rb[0].w};
            const float e1[4] = {rb[1].x, rb[1].y, rb[1].z, rb[1].w};
#pragma unroll
            for (int cc = 0; cc < 4; cc++) {
                const int n  = nq * 4 + cc;
                const int bi = (n >> 3) * 2 + ks16;
                uint32_t wh, wl;
                pack2_bf(e0[cc], e1[cc], wh, wl);
                uint32_t* base = bp + bi * 132 + ((n & 7) * 4 + tgk) * 4;
                base[breg]     = wh;
                base[breg + 2] = wl;
            }
        } else {
#pragma unroll
            for (int j = 0; j < 2; j++) {
                const int idx  = t + 256 * j;
                const int n    = idx >> 3;
                const int kq   = idx & 7;
                const int ks16 = kq >> 2;
                const int bi   = (n >> 3) * 2 + ks16;
                uint32_t* tb = bp + bi * 132 + ((n & 7) * 4) * 4;
                const float vals[4] = {rb[j].x, rb[j].y, rb[j].z, rb[j].w};
#pragma unroll
                for (int q = 0; q < 2; q++) {   // pairs (4kq+2q, +1)
                    const int pp   = (2 * kq + q) & 7;
                    const int breg = (pp >= 4) ? 1 : 0;
                    const int tgk  = pp & 3;
                    uint32_t wh, wl;
                    pack2_bf(vals[2 * q], vals[2 * q + 1], wh, wl);
                    uint32_t* base = tb + tgk * 4;
                    base[breg]     = wh;
                    base[breg + 2] = wl;
                }
            }
        }
    };
    // ---- compute one K-32 tile (2 x k16 steps)
    auto compute = [&](int bb) {
        const uint32_t* bp = s->Bp[bb];
#pragma unroll
        for (int ks = 0; ks < 2; ks++) {
            const int base = ks * 8;
            uint32_t ah[2][4], al[2][4];
#pragma unroll
            for (int mi = 0; mi < 2; mi++) {
                const int rm = wm * 32 + mi * 16 + group;
                ah[mi][0] = s->Ah[bb][rm][base + tg];
                ah[mi][1] = s->Ah[bb][rm + 8][base + tg];
                ah[mi][2] = s->Ah[bb][rm][base + tg + 4];
                ah[mi][3] = s->Ah[bb][rm + 8][base + tg + 4];
                al[mi][0] = s->Al[bb][rm][base + tg];
                al[mi][1] = s->Al[bb][rm + 8][base + tg];
                al[mi][2] = s->Al[bb][rm][base + tg + 4];
                al[mi][3] = s->Al[bb][rm + 8][base + tg + 4];
            }
#pragma unroll
            for (int ni = 0; ni < 4; ni++) {
                const uint32_t* Bf = bp + ((wn * 4 + ni) * 2 + ks) * 132 + lane * 4;
                uint4 bv = *reinterpret_cast<const uint4*>(Bf);
#pragma unroll
                for (int mi = 0; mi < 2; mi++) {
                    mma_bf16(c[mi][ni], ah[mi], bv.x, bv.y);   // hi*hi
                    mma_bf16(c[mi][ni], ah[mi], bv.z, bv.w);   // hi*lo
                    mma_bf16(c[mi][ni], al[mi], bv.x, bv.y);   // lo*hi
                }
            }
        }
    };

    // ---- pipelined main loop
    loadA(k0);
    loadB(k0);
    storeAB(0);
    __syncthreads();

    const int nkb = kchunk >> 5;
    for (int kb = 0; kb < nkb; kb++) {
        const int cur = kb & 1;
        if (kb + 1 < nkb) {
            loadA(k0 + (kb + 1) * 32);
            loadB(k0 + (kb + 1) * 32);
        }
        compute(cur);
        if (kb + 1 < nkb) storeAB(cur ^ 1);
        __syncthreads();
    }

    // ---- write partials
    float* pb = g_part + (size_t)blockIdx.y * (BB * N);
#pragma unroll
    for (int mi = 0; mi < 2; mi++) {
        const int row0 = wm * 32 + mi * 16 + group;
#pragma unroll
        for (int ni = 0; ni < 4; ni++) {
            const int col = n0 + wn * 32 + ni * 8 + 2 * tg;
            float2 v01 = {c[mi][ni][0], c[mi][ni][1]};
            float2 v23 = {c[mi][ni][2], c[mi][ni][3]};
            *reinterpret_cast<float2*>(pb + (size_t)row0 * N + col) = v01;
            *reinterpret_cast<float2*>(pb + (size_t)(row0 + 8) * N + col) = v23;
        }
    }
}

// =====================================================================
// Split-K reduce, compile-time S. OUTSEL: 0 -> out param, 1 -> g_decq
// =====================================================================
template <int OUTSEL, bool SCALE, int S>
__global__ void reduce_add_kernel(float* __restrict__ outp,
                                  const float* __restrict__ bias,
                                  int MN, int N) {
    float* out = (OUTSEL == 0) ? outp : (float*)g_decq;
    int i = (blockIdx.x * blockDim.x + threadIdx.x) * 4;
    if (i >= MN) return;
    float4 v[S];
#pragma unroll
    for (int k = 0; k < S; k++)
        v[k] = *reinterpret_cast<const float4*>(g_part + (size_t)k * MN + i);
    float4 sv = v[0];
#pragma unroll
    for (int k = 1; k < S; k++) {
        sv.x += v[k].x; sv.y += v[k].y; sv.z += v[k].z; sv.w += v[k].w;
    }
    if (SCALE) {
        const int m = i / N;
        const float inv = 1.f / (g_fden[m] + g_fden[BB + m]);
        sv.x *= inv; sv.y *= inv; sv.z *= inv; sv.w *= inv;
    }
    if (bias) {
        float4 bv = *reinterpret_cast<const float4*>(bias + (i % N));
        sv.x += bv.x; sv.y += bv.y; sv.z += bv.z; sv.w += bv.w;
    }
    *reinterpret_cast<float4*>(out + i) = sv;
}

// =====================================================================
// Fused attention pass. grid (BB, 2), 256 threads (8 warps).
// - Stages u[b] into smem by reducing the u-GEMM's USPLIT split-K partials.
// - Computes c[b] = bq . dec_q[b] inline.
// - One warp per encoder row: read row once (16 LDG.128 -> regs), dot vs u
//   (smem), shuffle-reduce, w = exp(tanh(dot+c)), accumulate w*x from REGS.
//   No syncthreads / re-reads in the main loop.
// - Cross-warp combine at the end via smem (fixed order).
// Writes UNNORMALIZED partial sums + partial denominators.
// =====================================================================
__global__ void __launch_bounds__(256, 1)
fused_attn_kernel(const float* __restrict__ enc, const float* __restrict__ bq) {
    const int b    = blockIdx.x;
    const int sp   = blockIdx.y;       // 0..1
    const int t    = threadIdx.x;      // 256
    const int warp = t >> 5;
    const int lane = t & 31;
    const int lstart = sp * 98;
    const int lend   = (lstart + 98 < LL) ? lstart + 98 : LL;

    extern __shared__ float smf[];
    float* u_s  = smf;            // [2048]
    float* sacc = smf + EE;       // [8][2048]
    __shared__ float cred[8];
    __shared__ float dwarp[8];
    __shared__ float c_sh;

    // ---- stage u[b] = sum of USPLIT u-GEMM partials
#pragma unroll
    for (int j = 0; j < 2; j++) {
        const int p = t + 256 * j;   // float4 index 0..511
        float4 a = *reinterpret_cast<const float4*>(g_part + (size_t)b * EE + 4 * p);
#pragma unroll
        for (int sK = 1; sK < USPLIT; sK++) {
            float4 v = *reinterpret_cast<const float4*>(
                g_part + (size_t)sK * (BB * EE) + (size_t)b * EE + 4 * p);
            a.x += v.x; a.y += v.y; a.z += v.z; a.w += v.w;
        }
        *reinterpret_cast<float4*>(u_s + 4 * p) = a;
    }

    // ---- c[b] = bq . dec_q[b] (fixed order)
    {
        const float* dq = g_decq + (size_t)b * AA;
        float cv = bq[t] * dq[t] + bq[t + 256] * dq[t + 256]
                 + bq[t + 512] * dq[t + 512] + bq[t + 768] * dq[t + 768];
#pragma unroll
        for (int o = 16; o > 0; o >>= 1) cv += __shfl_xor_sync(0xffffffffu, cv, o);
        if (lane == 0) cred[warp] = cv;
    }
    __syncthreads();
    if (t == 0) {
        float tot = 0.f;
        for (int i = 0; i < 8; i++) tot += cred[i];
        c_sh = tot;
    }
    __syncthreads();
    const float c_b = c_sh;

    const float4* encb4 = reinterpret_cast<const float4*>(enc + (size_t)b * LL * EE);
    const float4* us4   = reinterpret_cast<const float4*>(u_s);

    float4 ma[16];
#pragma unroll
    for (int i = 0; i < 16; i++) ma[i] = make_float4(0.f, 0.f, 0.f, 0.f);
    float den = 0.f;

    // ---- main loop: one warp per row
    for (int l = lstart + warp; l < lend; l += 8) {
        const float4* row = encb4 + (size_t)l * (EE / 4);
        float4 x[16];
#pragma unroll
        for (int i = 0; i < 16; i++) x[i] = row[lane + 32 * i];
        float d = 0.f;
#pragma unroll
        for (int i = 0; i < 16; i++) {
            float4 uu = us4[lane + 32 * i];
            d += x[i].x * uu.x + x[i].y * uu.y + x[i].z * uu.z + x[i].w * uu.w;
        }
#pragma unroll
        for (int o = 16; o > 0; o >>= 1) d += __shfl_xor_sync(0xffffffffu, d, o);
        // w = exp(tanh(d + c))
        const float z  = d + c_b;
        const float th = 1.f - __fdividef(2.f, __expf(2.f * z) + 1.f);
        const float w  = __expf(th);
        den += w;
#pragma unroll
        for (int i = 0; i < 16; i++) {
            ma[i].x += w * x[i].x; ma[i].y += w * x[i].y;
            ma[i].z += w * x[i].z; ma[i].w += w * x[i].w;
        }
    }

    // ---- cross-warp combine (fixed order)
    float4* sw = reinterpret_cast<float4*>(sacc + (size_t)warp * EE);
#pragma unroll
    for (int i = 0; i < 16; i++) sw[lane + 32 * i] = ma[i];
    if (lane == 0) dwarp[warp] = den;
    __syncthreads();

    float* pp = g_fpart + ((size_t)sp * BB + b) * EE;
#pragma unroll
    for (int j = 0; j < 2; j++) {
        const int p = t + 256 * j;   // float4 index
        float4 a = reinterpret_cast<const float4*>(sacc)[p];
#pragma unroll
        for (int wq = 1; wq < 8; wq++) {
            float4 v = reinterpret_cast<const float4*>(sacc + (size_t)wq * EE)[p];
            a.x += v.x; a.y += v.y; a.z += v.z; a.w += v.w;
        }
        reinterpret_cast<float4*>(pp)[p] = a;
    }
    if (t == 0) {
        float dt = 0.f;
        for (int i = 0; i < 8; i++) dt += dwarp[i];
        g_fden[sp * BB + b] = dt;
    }
}

// =====================================================================
// Launcher
// =====================================================================
extern "C" void kernel_launch(void* const* d_in, const int* in_sizes, int n_in,
                              void* d_out, int out_size) {
    const float* enc = (const float*)d_in[0];  // [128,196,2048]
    const float* dh  = (const float*)d_in[1];  // [128,1024]
    const float* Wq  = (const float*)d_in[2];  // [1024,2048]  (A,E)
    const float* bq  = (const float*)d_in[3];  // [1024]
    const float* Wv  = (const float*)d_in[4];  // [1024,2048]  (A,E)
    const float* bv  = (const float*)d_in[5];  // [1024]
    const float* Wd  = (const float*)d_in[6];  // [1024,1024]  (A,D)
    const float* bd  = (const float*)d_in[7];  // [1024]
    float* out = (float*)d_out;                // [128,1024]

    const int gsm = (int)sizeof(SmemGemm);     // ~57KB dynamic
    const int fsm = (EE + 8 * EE) * 4;         // 72KB dynamic
    cudaFuncSetAttribute(gemm_tc<false, 0>, cudaFuncAttributeMaxDynamicSharedMemorySize, gsm);
    cudaFuncSetAttribute(gemm_tc<true, 1>,  cudaFuncAttributeMaxDynamicSharedMemorySize, gsm);
    cudaFuncSetAttribute(gemm_tc<false, 2>, cudaFuncAttributeMaxDynamicSharedMemorySize, gsm);
    cudaFuncSetAttribute(fused_attn_kernel, cudaFuncAttributeMaxDynamicSharedMemorySize, fsm);

    // 1) dec_q = h @ Wd^T + bd   (NT, K=D=1024, split 8 -> 16x8 = 128 CTAs)
    gemm_tc<false, 0><<<dim3(AA / 64, 8), 256, gsm>>>(dh, Wd, DD, AA, DD / 8);
    reduce_add_kernel<1, false, 8><<<(BB * AA) / 1024, 256>>>(nullptr, bd, BB * AA, AA);

    // 2) u partials = dec_q @ Wq (NN, K=A=1024, split USPLIT -> 32x4 = 128 CTAs)
    //    (left as partials in g_part; fused kernel reduces them while staging u)
    gemm_tc<true, 1><<<dim3(EE / 64, USPLIT), 256, gsm>>>(nullptr, Wq, AA, EE, AA / USPLIT);

    // 3) fused: u-reduce + c + energies + weights + weighted encoder sum
    fused_attn_kernel<<<dim3(BB, 2), 256, fsm>>>(enc, bq);

    // 4) context = (P0+P1) @ Wv^T, then *1/sum(w) + bv in reduce epilogue
    //    (NT, K=E=2048, split 8 -> 16x8 = 128 CTAs)
    gemm_tc<false, 2><<<dim3(AA / 64, 8), 256, gsm>>>(nullptr, Wv, EE, AA, EE / 8);
    reduce_add_kernel<0, true, 8><<<(BB * AA) / 1024, 256>>>(out, bv, BB * AA, AA);
}

// round 7
// speedup vs baseline: 1.9331x; 1.0472x over previous
#include <cuda_runtime.h>
#include <cstdint>

// Problem constants
#define BB   128   // batch
#define LL   196   // encoder length
#define EE   2048  // encoder dim
#define DD   1024  // decoder dim
#define AA   1024  // attention dim
#define USPLIT 4   // split-K of the u GEMM (fused kernel reduces these partials)

// ---------------- device scratch (no allocations allowed) ----------------
__device__ float g_decq[BB * AA];        // Wd @ h + bd           [128,1024]
__device__ float g_part[1 << 21];        // 8MB split-K partials (reused)
__device__ float g_fpart[2 * BB * EE];   // fused partial sums (unnormalized)
__device__ float g_fden[2 * BB];         // fused partial denominators

// ---------------- bf16 split helpers ----------------
__device__ __forceinline__ void pack2_bf(float x0, float x1,
                                         uint32_t& wh, uint32_t& wl) {
    asm("cvt.rn.bf16x2.f32 %0, %1, %2;" : "=r"(wh) : "f"(x1), "f"(x0));
    float h0 = __uint_as_float(wh << 16);
    float h1 = __uint_as_float(wh & 0xffff0000u);
    float l0 = x0 - h0;
    float l1 = x1 - h1;
    asm("cvt.rn.bf16x2.f32 %0, %1, %2;" : "=r"(wl) : "f"(l1), "f"(l0));
}

__device__ __forceinline__ void mma_bf16(float* c, const uint32_t* a,
                                         uint32_t b0, uint32_t b1) {
    asm volatile(
        "mma.sync.aligned.m16n8k16.row.col.f32.bf16.bf16.f32 "
        "{%0,%1,%2,%3}, {%4,%5,%6,%7}, {%8,%9}, {%0,%1,%2,%3};"
        : "+f"(c[0]), "+f"(c[1]), "+f"(c[2]), "+f"(c[3])
        : "r"(a[0]), "r"(a[1]), "r"(a[2]), "r"(a[3]), "r"(b0), "r"(b1));
}

// Smem: A planes [row][kpair] stride 20 (conflict-free frag reads),
// B packed fragment-major (see R5/R6 layout notes).
struct SmemGemm {
    uint32_t Ah[2][128][20];
    uint32_t Al[2][128][20];
    uint32_t Bp[2][16 * 132];
};

// =====================================================================
// Tensor-core bf16x3 GEMM, split-K partials (unchanged from R6).
// =====================================================================
template <bool NN, int XSEL>
__global__ void __launch_bounds__(256, 2)
gemm_tc(const float* __restrict__ Xp, const float* __restrict__ W,
        int K, int N, int kchunk) {
    extern __shared__ SmemGemm sm_g[];
    SmemGemm* s = sm_g;

    const float* X = (XSEL == 1) ? (const float*)g_decq : Xp;

    const int t     = threadIdx.x;
    const int warp  = t >> 5;
    const int lane  = t & 31;
    const int group = lane >> 2;
    const int tg    = lane & 3;
    const int wm    = warp & 3;
    const int wn    = warp >> 2;
    const int n0    = blockIdx.x * 64;
    const int k0    = blockIdx.y * kchunk;

    float c[2][4][4];
#pragma unroll
    for (int mi = 0; mi < 2; mi++)
#pragma unroll
        for (int ni = 0; ni < 4; ni++)
#pragma unroll
            for (int r = 0; r < 4; r++) c[mi][ni][r] = 0.f;

    float4 ra[4];
    float4 rb[2];

    auto loadA = [&](int kt) {
#pragma unroll
        for (int j = 0; j < 4; j++) {
            const int idx = t + 256 * j;
            const int row = idx >> 3;
            const int kq  = idx & 7;
            if (XSEL == 2) {
                float4 p0 = *reinterpret_cast<const float4*>(
                    g_fpart + (size_t)row * EE + kt + kq * 4);
                float4 p1 = *reinterpret_cast<const float4*>(
                    g_fpart + (size_t)(BB + row) * EE + kt + kq * 4);
                ra[j] = make_float4(p0.x + p1.x, p0.y + p1.y, p0.z + p1.z, p0.w + p1.w);
            } else {
                ra[j] = *reinterpret_cast<const float4*>(X + (size_t)row * K + kt + kq * 4);
            }
        }
    };
    auto loadB = [&](int kt) {
        if (NN) {
            const int kp = t >> 4;
            const int nq = t & 15;
            rb[0] = *reinterpret_cast<const float4*>(W + (size_t)(kt + 2 * kp) * N + n0 + nq * 4);
            rb[1] = *reinterpret_cast<const float4*>(W + (size_t)(kt + 2 * kp + 1) * N + n0 + nq * 4);
        } else {
#pragma unroll
            for (int j = 0; j < 2; j++) {
                const int idx = t + 256 * j;
                const int n   = idx >> 3;
                const int kq  = idx & 7;
                rb[j] = *reinterpret_cast<const float4*>(W + (size_t)(n0 + n) * K + kt + kq * 4);
            }
        }
    };
    auto storeAB = [&](int bb) {
#pragma unroll
        for (int j = 0; j < 4; j++) {
            const int idx = t + 256 * j;
            const int row = idx >> 3;
            const int kq  = idx & 7;
            uint32_t wh0, wl0, wh1, wl1;
            pack2_bf(ra[j].x, ra[j].y, wh0, wl0);
            pack2_bf(ra[j].z, ra[j].w, wh1, wl1);
            *reinterpret_cast<uint2*>(&s->Ah[bb][row][2 * kq]) = make_uint2(wh0, wh1);
            *reinterpret_cast<uint2*>(&s->Al[bb][row][2 * kq]) = make_uint2(wl0, wl1);
        }
        uint32_t* bp = s->Bp[bb];
        if (NN) {
            const int kp   = t >> 4;
            const int nq   = t & 15;
            const int ks16 = kp >> 3;
            const int pp   = kp & 7;
            const int breg = (pp >= 4) ? 1 : 0;
            const int tgk  = pp & 3;
            const float e0[4] = {rb[0].x, rb[0].y, rb[0].z, rb[0].w};
            const float e1[4] = {rb[1].x, rb[1].y, rb[1].z, rb[1].w};
#pragma unroll
            for (int cc = 0; cc < 4; cc++) {
                const int n  = nq * 4 + cc;
                const int bi = (n >> 3) * 2 + ks16;
                uint32_t wh, wl;
                pack2_bf(e0[cc], e1[cc], wh, wl);
                uint32_t* base = bp + bi * 132 + ((n & 7) * 4 + tgk) * 4;
                base[breg]     = wh;
                base[breg + 2] = wl;
            }
        } else {
#pragma unroll
            for (int j = 0; j < 2; j++) {
                const int idx  = t + 256 * j;
                const int n    = idx >> 3;
                const int kq   = idx & 7;
                const int ks16 = kq >> 2;
                const int bi   = (n >> 3) * 2 + ks16;
                uint32_t* tb = bp + bi * 132 + ((n & 7) * 4) * 4;
                const float vals[4] = {rb[j].x, rb[j].y, rb[j].z, rb[j].w};
#pragma unroll
                for (int q = 0; q < 2; q++) {
                    const int pp   = (2 * kq + q) & 7;
                    const int breg = (pp >= 4) ? 1 : 0;
                    const int tgk  = pp & 3;
                    uint32_t wh, wl;
                    pack2_bf(vals[2 * q], vals[2 * q + 1], wh, wl);
                    uint32_t* base = tb + tgk * 4;
                    base[breg]     = wh;
                    base[breg + 2] = wl;
                }
            }
        }
    };
    auto compute = [&](int bb) {
        const uint32_t* bp = s->Bp[bb];
#pragma unroll
        for (int ks = 0; ks < 2; ks++) {
            const int base = ks * 8;
            uint32_t ah[2][4], al[2][4];
#pragma unroll
            for (int mi = 0; mi < 2; mi++) {
                const int rm = wm * 32 + mi * 16 + group;
                ah[mi][0] = s->Ah[bb][rm][base + tg];
                ah[mi][1] = s->Ah[bb][rm + 8][base + tg];
                ah[mi][2] = s->Ah[bb][rm][base + tg + 4];
                ah[mi][3] = s->Ah[bb][rm + 8][base + tg + 4];
                al[mi][0] = s->Al[bb][rm][base + tg];
                al[mi][1] = s->Al[bb][rm + 8][base + tg];
                al[mi][2] = s->Al[bb][rm][base + tg + 4];
                al[mi][3] = s->Al[bb][rm + 8][base + tg + 4];
            }
#pragma unroll
            for (int ni = 0; ni < 4; ni++) {
                const uint32_t* Bf = bp + ((wn * 4 + ni) * 2 + ks) * 132 + lane * 4;
                uint4 bv = *reinterpret_cast<const uint4*>(Bf);
#pragma unroll
                for (int mi = 0; mi < 2; mi++) {
                    mma_bf16(c[mi][ni], ah[mi], bv.x, bv.y);
                    mma_bf16(c[mi][ni], ah[mi], bv.z, bv.w);
                    mma_bf16(c[mi][ni], al[mi], bv.x, bv.y);
                }
            }
        }
    };

    loadA(k0);
    loadB(k0);
    storeAB(0);
    __syncthreads();

    const int nkb = kchunk >> 5;
    for (int kb = 0; kb < nkb; kb++) {
        const int cur = kb & 1;
        if (kb + 1 < nkb) {
            loadA(k0 + (kb + 1) * 32);
            loadB(k0 + (kb + 1) * 32);
        }
        compute(cur);
        if (kb + 1 < nkb) storeAB(cur ^ 1);
        __syncthreads();
    }

    float* pb = g_part + (size_t)blockIdx.y * (BB * N);
#pragma unroll
    for (int mi = 0; mi < 2; mi++) {
        const int row0 = wm * 32 + mi * 16 + group;
#pragma unroll
        for (int ni = 0; ni < 4; ni++) {
            const int col = n0 + wn * 32 + ni * 8 + 2 * tg;
            float2 v01 = {c[mi][ni][0], c[mi][ni][1]};
            float2 v23 = {c[mi][ni][2], c[mi][ni][3]};
            *reinterpret_cast<float2*>(pb + (size_t)row0 * N + col) = v01;
            *reinterpret_cast<float2*>(pb + (size_t)(row0 + 8) * N + col) = v23;
        }
    }
}

// =====================================================================
// Split-K reduce, compile-time S. OUTSEL: 0 -> out param, 1 -> g_decq
// =====================================================================
template <int OUTSEL, bool SCALE, int S>
__global__ void reduce_add_kernel(float* __restrict__ outp,
                                  const float* __restrict__ bias,
                                  int MN, int N) {
    float* out = (OUTSEL == 0) ? outp : (float*)g_decq;
    int i = (blockIdx.x * blockDim.x + threadIdx.x) * 4;
    if (i >= MN) return;
    float4 v[S];
#pragma unroll
    for (int k = 0; k < S; k++)
        v[k] = *reinterpret_cast<const float4*>(g_part + (size_t)k * MN + i);
    float4 sv = v[0];
#pragma unroll
    for (int k = 1; k < S; k++) {
        sv.x += v[k].x; sv.y += v[k].y; sv.z += v[k].z; sv.w += v[k].w;
    }
    if (SCALE) {
        const int m = i / N;
        const float inv = 1.f / (g_fden[m] + g_fden[BB + m]);
        sv.x *= inv; sv.y *= inv; sv.z *= inv; sv.w *= inv;
    }
    if (bias) {
        float4 bv = *reinterpret_cast<const float4*>(bias + (i % N));
        sv.x += bv.x; sv.y += bv.y; sv.z += bv.z; sv.w += bv.w;
    }
    *reinterpret_cast<float4*>(out + i) = sv;
}

// =====================================================================
// Fused attention pass. grid (BB, 2), 256 threads = 8 warps = 4 warp PAIRS.
// Pair-of-warps per row: each warp owns HALF a row (x[8] float4 regs),
// half-dots combined via per-pair smem + named barrier (parity buffered).
// Registers ~110 -> 2 CTAs/SM -> all 256 CTAs resident in one wave.
// - Stages u[b] by reducing the u-GEMM's USPLIT split-K partials.
// - Computes c[b] = bq . dec_q[b] inline.
// Writes UNNORMALIZED partial sums + partial denominators.
// =====================================================================
__global__ void __launch_bounds__(256, 2)
fused_attn_kernel(const float* __restrict__ enc, const float* __restrict__ bq) {
    const int b    = blockIdx.x;
    const int sp   = blockIdx.y;       // 0..1
    const int t    = threadIdx.x;      // 256
    const int warp = t >> 5;
    const int lane = t & 31;
    const int pair = warp >> 1;        // 0..3
    const int half = warp & 1;         // 0/1 : which half of the row
    const int lstart = sp * 98;
    const int lend   = (lstart + 98 < LL) ? lstart + 98 : LL;

    extern __shared__ float smf[];
    float* u_s  = smf;                 // [2048]
    float* sacc = smf + EE;            // [4][2048] per-pair row accumulators
    __shared__ float cred[8];
    __shared__ float dpair[4];
    __shared__ float pd[4][2][2];      // [pair][parity][half]
    __shared__ float c_sh;

    // ---- stage u[b] = sum of USPLIT u-GEMM partials
#pragma unroll
    for (int j = 0; j < 2; j++) {
        const int p = t + 256 * j;     // float4 index 0..511
        float4 a = *reinterpret_cast<const float4*>(g_part + (size_t)b * EE + 4 * p);
#pragma unroll
        for (int sK = 1; sK < USPLIT; sK++) {
            float4 v = *reinterpret_cast<const float4*>(
                g_part + (size_t)sK * (BB * EE) + (size_t)b * EE + 4 * p);
            a.x += v.x; a.y += v.y; a.z += v.z; a.w += v.w;
        }
        *reinterpret_cast<float4*>(u_s + 4 * p) = a;
    }

    // ---- c[b] = bq . dec_q[b] (fixed order)
    {
        const float* dq = g_decq + (size_t)b * AA;
        float cv = bq[t] * dq[t] + bq[t + 256] * dq[t + 256]
                 + bq[t + 512] * dq[t + 512] + bq[t + 768] * dq[t + 768];
#pragma unroll
        for (int o = 16; o > 0; o >>= 1) cv += __shfl_xor_sync(0xffffffffu, cv, o);
        if (lane == 0) cred[warp] = cv;
    }
    __syncthreads();
    if (t == 0) {
        float tot = 0.f;
        for (int i = 0; i < 8; i++) tot += cred[i];
        c_sh = tot;
    }
    __syncthreads();
    const float c_b = c_sh;

    // warp's half-row base (float4 units)
    const float4* encb4 = reinterpret_cast<const float4*>(enc + (size_t)b * LL * EE)
                        + half * 256;
    const float4* us4   = reinterpret_cast<const float4*>(u_s) + half * 256;

    float4 ma[8];
#pragma unroll
    for (int i = 0; i < 8; i++) ma[i] = make_float4(0.f, 0.f, 0.f, 0.f);
    float den = 0.f;

    const int barid = pair + 1;        // named barriers 1..4, 64 threads each

    // ---- main loop: one warp-pair per row, 4 rows in flight per CTA
    int parity = 0;
    for (int l = lstart + pair; l < lend; l += 4, parity ^= 1) {
        const float4* row = encb4 + (size_t)l * (EE / 4);
        float4 x[8];
#pragma unroll
        for (int i = 0; i < 8; i++) x[i] = row[lane + 32 * i];
        float d = 0.f;
#pragma unroll
        for (int i = 0; i < 8; i++) {
            float4 uu = us4[lane + 32 * i];
            d += x[i].x * uu.x + x[i].y * uu.y + x[i].z * uu.z + x[i].w * uu.w;
        }
#pragma unroll
        for (int o = 16; o > 0; o >>= 1) d += __shfl_xor_sync(0xffffffffu, d, o);
        if (lane == 0) pd[pair][parity][half] = d;
        asm volatile("bar.sync %0, 64;" :: "r"(barid) : "memory");
        const float z  = pd[pair][parity][0] + pd[pair][parity][1] + c_b;
        const float th = 1.f - __fdividef(2.f, __expf(2.f * z) + 1.f);
        const float w  = __expf(th);
        if (half == 0) den += w;
#pragma unroll
        for (int i = 0; i < 8; i++) {
            ma[i].x += w * x[i].x; ma[i].y += w * x[i].y;
            ma[i].z += w * x[i].z; ma[i].w += w * x[i].w;
        }
    }

    // ---- per-pair store, then cross-pair combine (fixed order)
    float4* sw = reinterpret_cast<float4*>(sacc + (size_t)pair * EE) + half * 256;
#pragma unroll
    for (int i = 0; i < 8; i++) sw[lane + 32 * i] = ma[i];
    if (half == 0 && lane == 0) dpair[pair] = den;
    __syncthreads();

    float* pp = g_fpart + ((size_t)sp * BB + b) * EE;
#pragma unroll
    for (int j = 0; j < 2; j++) {
        const int p = t + 256 * j;     // float4 index 0..511
        float4 a = reinterpret_cast<const float4*>(sacc)[p];
#pragma unroll
        for (int q = 1; q < 4; q++) {
            float4 v = reinterpret_cast<const float4*>(sacc + (size_t)q * EE)[p];
            a.x += v.x; a.y += v.y; a.z += v.z; a.w += v.w;
        }
        reinterpret_cast<float4*>(pp)[p] = a;
    }
    if (t == 0) {
        float dt = 0.f;
        for (int i = 0; i < 4; i++) dt += dpair[i];
        g_fden[sp * BB + b] = dt;
    }
}

// =====================================================================
// Launcher
// =====================================================================
extern "C" void kernel_launch(void* const* d_in, const int* in_sizes, int n_in,
                              void* d_out, int out_size) {
    const float* enc = (const float*)d_in[0];  // [128,196,2048]
    const float* dh  = (const float*)d_in[1];  // [128,1024]
    const float* Wq  = (const float*)d_in[2];  // [1024,2048]  (A,E)
    const float* bq  = (const float*)d_in[3];  // [1024]
    const float* Wv  = (const float*)d_in[4];  // [1024,2048]  (A,E)
    const float* bv  = (const float*)d_in[5];  // [1024]
    const float* Wd  = (const float*)d_in[6];  // [1024,1024]  (A,D)
    const float* bd  = (const float*)d_in[7];  // [1024]
    float* out = (float*)d_out;                // [128,1024]

    const int gsm = (int)sizeof(SmemGemm);     // ~57KB dynamic
    const int fsm = (EE + 4 * EE) * 4;         // 40KB dynamic
    cudaFuncSetAttribute(gemm_tc<false, 0>, cudaFuncAttributeMaxDynamicSharedMemorySize, gsm);
    cudaFuncSetAttribute(gemm_tc<true, 1>,  cudaFuncAttributeMaxDynamicSharedMemorySize, gsm);
    cudaFuncSetAttribute(gemm_tc<false, 2>, cudaFuncAttributeMaxDynamicSharedMemorySize, gsm);
    cudaFuncSetAttribute(fused_attn_kernel, cudaFuncAttributeMaxDynamicSharedMemorySize, fsm);

    // 1) dec_q = h @ Wd^T + bd   (NT, K=D=1024, split 8 -> 16x8 = 128 CTAs)
    gemm_tc<false, 0><<<dim3(AA / 64, 8), 256, gsm>>>(dh, Wd, DD, AA, DD / 8);
    reduce_add_kernel<1, false, 8><<<(BB * AA) / 1024, 256>>>(nullptr, bd, BB * AA, AA);

    // 2) u partials = dec_q @ Wq (NN, K=A=1024, split USPLIT -> 32x4 = 128 CTAs)
    gemm_tc<true, 1><<<dim3(EE / 64, USPLIT), 256, gsm>>>(nullptr, Wq, AA, EE, AA / USPLIT);

    // 3) fused: u-reduce + c + energies + weights + weighted encoder sum
    fused_attn_kernel<<<dim3(BB, 2), 256, fsm>>>(enc, bq);

    // 4) context = (P0+P1) @ Wv^T, then *1/sum(w) + bv in reduce epilogue
    gemm_tc<false, 2><<<dim3(AA / 64, 8), 256, gsm>>>(nullptr, Wv, EE, AA, EE / 8);
    reduce_add_kernel<0, true, 8><<<(BB * AA) / 1024, 256>>>(out, bv, BB * AA, AA);
}